// round 1
// baseline (speedup 1.0000x reference)
#include <cuda_runtime.h>
#include <math.h>

#define TOK   2048          // B*S tokens
#define HD    1024
#define NHEAD 16
#define DH    64
#define NEXP  8
#define FF    4096
#define SEQ   1024

// ---------------- scratch (device globals: allocation-guard safe) ----------------
__device__ float g_h1[TOK * HD];
__device__ float g_q [TOK * HD];
__device__ float g_k [TOK * HD];
__device__ float g_v [TOK * HD];
__device__ float g_attn[TOK * HD];
__device__ float g_x1[TOK * HD];
__device__ float g_h2[TOK * HD];
__device__ float g_we[TOK * NEXP];
__device__ float g_usage[NEXP];
__device__ int   g_cnt[NEXP];
__device__ int   g_idx[NEXP * TOK];
__device__ float g_hg[(size_t)NEXP * TOK * FF];   // per-expert hidden activations

// ---------------- init ----------------
__global__ void init_kernel() {
    int t = threadIdx.x;
    if (t < NEXP) { g_cnt[t] = 0; g_usage[t] = 0.f; }
}

// ---------------- layernorm: one block per row ----------------
__global__ void ln_kernel(const float* __restrict__ x, const float* __restrict__ g,
                          const float* __restrict__ b, float* __restrict__ y) {
    __shared__ float red[256];
    int row = blockIdx.x;
    const float* xr = x + (size_t)row * HD;
    float s = 0.f;
    for (int i = threadIdx.x; i < HD; i += 256) s += xr[i];
    red[threadIdx.x] = s; __syncthreads();
    for (int o = 128; o > 0; o >>= 1) {
        if (threadIdx.x < o) red[threadIdx.x] += red[threadIdx.x + o];
        __syncthreads();
    }
    float mu = red[0] * (1.f / HD);
    __syncthreads();
    float v = 0.f;
    for (int i = threadIdx.x; i < HD; i += 256) { float d = xr[i] - mu; v += d * d; }
    red[threadIdx.x] = v; __syncthreads();
    for (int o = 128; o > 0; o >>= 1) {
        if (threadIdx.x < o) red[threadIdx.x] += red[threadIdx.x + o];
        __syncthreads();
    }
    float rstd = rsqrtf(red[0] * (1.f / HD) + 1e-5f);
    float* yr = y + (size_t)row * HD;
    for (int i = threadIdx.x; i < HD; i += 256)
        yr[i] = (xr[i] - mu) * rstd * g[i] + b[i];
}

// ---------------- NT GEMM: C[M,N] = A[M,K] @ B[N,K]^T (+ optional residual) ----------------
// 64x64 tile, BK=16, 256 threads, 4x4 microtile. M,N multiples of 64.
template <bool ADD_RES>
__global__ void gemm_nt_kernel(const float* __restrict__ A, const float* __restrict__ Bm,
                               const float* __restrict__ Res, float* __restrict__ C,
                               int Ncols, int K) {
    __shared__ float As[16][68];
    __shared__ float Bs[16][68];
    int tid = threadIdx.x;
    int tx = tid & 15, ty = tid >> 4;
    int rowBase = blockIdx.y * 64, colBase = blockIdx.x * 64;
    int la_r = tid >> 2;          // 0..63
    int la_k = (tid & 3) * 4;     // 0,4,8,12
    const float* Ap = A  + (size_t)(rowBase + la_r) * K + la_k;
    const float* Bp = Bm + (size_t)(colBase + la_r) * K + la_k;
    float acc[4][4] = {};
    for (int k0 = 0; k0 < K; k0 += 16) {
        float4 av = *(const float4*)(Ap + k0);
        float4 bv = *(const float4*)(Bp + k0);
        As[la_k + 0][la_r] = av.x; As[la_k + 1][la_r] = av.y;
        As[la_k + 2][la_r] = av.z; As[la_k + 3][la_r] = av.w;
        Bs[la_k + 0][la_r] = bv.x; Bs[la_k + 1][la_r] = bv.y;
        Bs[la_k + 2][la_r] = bv.z; Bs[la_k + 3][la_r] = bv.w;
        __syncthreads();
#pragma unroll
        for (int kk = 0; kk < 16; kk++) {
            float4 af = *(const float4*)&As[kk][ty * 4];
            float4 bf = *(const float4*)&Bs[kk][tx * 4];
            float avr[4] = {af.x, af.y, af.z, af.w};
            float bvr[4] = {bf.x, bf.y, bf.z, bf.w};
#pragma unroll
            for (int i = 0; i < 4; i++)
#pragma unroll
                for (int j = 0; j < 4; j++)
                    acc[i][j] += avr[i] * bvr[j];
        }
        __syncthreads();
    }
#pragma unroll
    for (int i = 0; i < 4; i++) {
        int r = rowBase + ty * 4 + i;
        float4 o = make_float4(acc[i][0], acc[i][1], acc[i][2], acc[i][3]);
        if (ADD_RES) {
            float4 rv = *(const float4*)(Res + (size_t)r * Ncols + colBase + tx * 4);
            o.x += rv.x; o.y += rv.y; o.z += rv.z; o.w += rv.w;
        }
        *(float4*)(C + (size_t)r * Ncols + colBase + tx * 4) = o;
    }
}

// ---------------- flash attention (causal, fp32) ----------------
// grid: (q_tiles=16, b*h=32). 256 threads, 64-query x 64-dim accumulators.
__global__ void attn_kernel() {
    extern __shared__ float sm[];
    float (*Qs)[68]  = (float(*)[68])sm;                 // [dim][row]
    float (*KVs)[68] = (float(*)[68])(sm + 64 * 68);     // K: [dim][key]; V: [key][dim]
    float (*Ps)[68]  = (float(*)[68])(sm + 2 * 64 * 68); // probabilities [row][key]
    int qt = blockIdx.x;
    int bh = blockIdx.y;
    int b = bh >> 4, h = bh & 15;
    int tid = threadIdx.x;
    int tx = tid & 15, ty = tid >> 4;
    int lr = tid >> 2;            // 0..63
    int lk = (tid & 3) * 4;       // 0,4,8,12

    // load Q tile (transposed to [dim][row])
    {
        const float* qp = g_q + (size_t)(b * SEQ + qt * 64 + lr) * HD + h * DH;
#pragma unroll
        for (int p = 0; p < 4; p++) {
            float4 v = *(const float4*)(qp + lk + p * 16);
            int d0 = lk + p * 16;
            Qs[d0 + 0][lr] = v.x; Qs[d0 + 1][lr] = v.y;
            Qs[d0 + 2][lr] = v.z; Qs[d0 + 3][lr] = v.w;
        }
    }
    float m_i[4], l_i[4], outAcc[4][4];
#pragma unroll
    for (int i = 0; i < 4; i++) {
        m_i[i] = -1e30f; l_i[i] = 0.f;
#pragma unroll
        for (int j = 0; j < 4; j++) outAcc[i][j] = 0.f;
    }
    __syncthreads();

    for (int kt = 0; kt <= qt; kt++) {
        // load K tile transposed
        {
            const float* kp = g_k + (size_t)(b * SEQ + kt * 64 + lr) * HD + h * DH;
#pragma unroll
            for (int p = 0; p < 4; p++) {
                float4 v = *(const float4*)(kp + lk + p * 16);
                int d0 = lk + p * 16;
                KVs[d0 + 0][lr] = v.x; KVs[d0 + 1][lr] = v.y;
                KVs[d0 + 2][lr] = v.z; KVs[d0 + 3][lr] = v.w;
            }
        }
        __syncthreads();

        float s[4][4] = {};
#pragma unroll 16
        for (int kk = 0; kk < 64; kk++) {
            float4 af = *(const float4*)&Qs[kk][ty * 4];
            float4 bf = *(const float4*)&KVs[kk][tx * 4];
            float avr[4] = {af.x, af.y, af.z, af.w};
            float bvr[4] = {bf.x, bf.y, bf.z, bf.w};
#pragma unroll
            for (int i = 0; i < 4; i++)
#pragma unroll
                for (int j = 0; j < 4; j++)
                    s[i][j] += avr[i] * bvr[j];
        }
        // scale + causal mask
        if (kt == qt) {
#pragma unroll
            for (int i = 0; i < 4; i++)
#pragma unroll
                for (int j = 0; j < 4; j++) {
                    int r = ty * 4 + i, c = tx * 4 + j;
                    s[i][j] = (c > r) ? -1e30f : s[i][j] * 0.125f;
                }
        } else {
#pragma unroll
            for (int i = 0; i < 4; i++)
#pragma unroll
                for (int j = 0; j < 4; j++) s[i][j] *= 0.125f;
        }
        // online softmax; row groups = half-warps (ty fixed within half-warp)
#pragma unroll
        for (int i = 0; i < 4; i++) {
            float rmax = fmaxf(fmaxf(s[i][0], s[i][1]), fmaxf(s[i][2], s[i][3]));
#pragma unroll
            for (int o = 8; o > 0; o >>= 1)
                rmax = fmaxf(rmax, __shfl_xor_sync(0xffffffffu, rmax, o));
            float mnew = fmaxf(m_i[i], rmax);
            float rsum = 0.f;
#pragma unroll
            for (int j = 0; j < 4; j++) { float p = __expf(s[i][j] - mnew); s[i][j] = p; rsum += p; }
#pragma unroll
            for (int o = 8; o > 0; o >>= 1)
                rsum += __shfl_xor_sync(0xffffffffu, rsum, o);
            float alpha = __expf(m_i[i] - mnew);
            l_i[i] = l_i[i] * alpha + rsum;
            m_i[i] = mnew;
#pragma unroll
            for (int j = 0; j < 4; j++) outAcc[i][j] *= alpha;
            *(float4*)&Ps[ty * 4 + i][tx * 4] = make_float4(s[i][0], s[i][1], s[i][2], s[i][3]);
        }
        __syncthreads();   // Ps complete; KVs free to reuse

        // load V tile natural [key][dim]
        {
            const float* vp = g_v + (size_t)(b * SEQ + kt * 64 + lr) * HD + h * DH;
#pragma unroll
            for (int p = 0; p < 4; p++) {
                float4 v = *(const float4*)(vp + lk + p * 16);
                *(float4*)&KVs[lr][lk + p * 16] = v;
            }
        }
        __syncthreads();

#pragma unroll 16
        for (int jj = 0; jj < 64; jj++) {
            float4 bf = *(const float4*)&KVs[jj][tx * 4];
            float p0 = Ps[ty * 4 + 0][jj], p1 = Ps[ty * 4 + 1][jj];
            float p2 = Ps[ty * 4 + 2][jj], p3 = Ps[ty * 4 + 3][jj];
            outAcc[0][0] += p0 * bf.x; outAcc[0][1] += p0 * bf.y; outAcc[0][2] += p0 * bf.z; outAcc[0][3] += p0 * bf.w;
            outAcc[1][0] += p1 * bf.x; outAcc[1][1] += p1 * bf.y; outAcc[1][2] += p1 * bf.z; outAcc[1][3] += p1 * bf.w;
            outAcc[2][0] += p2 * bf.x; outAcc[2][1] += p2 * bf.y; outAcc[2][2] += p2 * bf.z; outAcc[2][3] += p2 * bf.w;
            outAcc[3][0] += p3 * bf.x; outAcc[3][1] += p3 * bf.y; outAcc[3][2] += p3 * bf.z; outAcc[3][3] += p3 * bf.w;
        }
        __syncthreads();
    }
    // finalize
#pragma unroll
    for (int i = 0; i < 4; i++) {
        float inv = 1.f / l_i[i];
        int q = qt * 64 + ty * 4 + i;
        float4 o = make_float4(outAcc[i][0] * inv, outAcc[i][1] * inv,
                               outAcc[i][2] * inv, outAcc[i][3] * inv);
        *(float4*)(g_attn + (size_t)(b * SEQ + q) * HD + h * DH + tx * 4) = o;
    }
}

// ---------------- router: one warp per token ----------------
__global__ void router_kernel(const float* __restrict__ Wr) {
    int gwarp = (blockIdx.x * blockDim.x + threadIdx.x) >> 5;
    int lane = threadIdx.x & 31;
    if (gwarp >= TOK) return;
    const float* xr = g_h2 + (size_t)gwarp * HD;
    float acc[NEXP] = {};
    for (int i = lane; i < HD; i += 32) {
        float xv = xr[i];
#pragma unroll
        for (int e = 0; e < NEXP; e++) acc[e] += xv * Wr[e * HD + i];
    }
#pragma unroll
    for (int e = 0; e < NEXP; e++)
#pragma unroll
        for (int o = 16; o > 0; o >>= 1)
            acc[e] += __shfl_xor_sync(0xffffffffu, acc[e], o);
    if (lane == 0) {
        // full softmax -> usage (for lb_loss)
        float mx = acc[0];
#pragma unroll
        for (int e = 1; e < NEXP; e++) mx = fmaxf(mx, acc[e]);
        float p[NEXP], se = 0.f;
#pragma unroll
        for (int e = 0; e < NEXP; e++) { p[e] = __expf(acc[e] - mx); se += p[e]; }
        float inv = 1.f / (se * (float)TOK);
#pragma unroll
        for (int e = 0; e < NEXP; e++) atomicAdd(&g_usage[e], p[e] * inv);
        // top-2 (ties -> lower index, matching top_k)
        int i0 = 0;
#pragma unroll
        for (int e = 1; e < NEXP; e++) if (acc[e] > acc[i0]) i0 = e;
        int i1 = (i0 == 0) ? 1 : 0;
#pragma unroll
        for (int e = 0; e < NEXP; e++) if (e != i0 && acc[e] > acc[i1]) i1 = e;
        float l0 = acc[i0], l1 = acc[i1];
        float m2 = fmaxf(l0, l1);
        float e0 = __expf(l0 - m2), e1 = __expf(l1 - m2);
        float s2 = e0 + e1;
        g_we[gwarp * NEXP + i0] = e0 / s2;
        g_we[gwarp * NEXP + i1] = e1 / s2;
        int p0 = atomicAdd(&g_cnt[i0], 1); g_idx[i0 * TOK + p0] = gwarp;
        int p1 = atomicAdd(&g_cnt[i1], 1); g_idx[i1 * TOK + p1] = gwarp;
    }
}

// ---------------- MoE up: hg = silu(x @ W1^T) * (x @ W3^T), gathered rows ----------------
__global__ void moe_up_kernel(const float* __restrict__ W1, const float* __restrict__ W3) {
    int e = blockIdx.z;
    int cnt = g_cnt[e];
    int rowBase = blockIdx.y * 64;
    if (rowBase >= cnt) return;
    int colBase = blockIdx.x * 64;
    __shared__ float As[16][68], B1s[16][68], B3s[16][68];
    __shared__ int rows[64];
    int tid = threadIdx.x;
    if (tid < 64) {
        int r = rowBase + tid;
        rows[tid] = g_idx[e * TOK + (r < cnt ? r : 0)];
    }
    __syncthreads();
    int tx = tid & 15, ty = tid >> 4;
    int la_r = tid >> 2, la_k = (tid & 3) * 4;
    const float* Ap  = g_h2 + (size_t)rows[la_r] * HD + la_k;
    const float* B1p = W1 + (size_t)e * FF * HD + (size_t)(colBase + la_r) * HD + la_k;
    const float* B3p = W3 + (size_t)e * FF * HD + (size_t)(colBase + la_r) * HD + la_k;
    float acc1[4][4] = {}, acc3[4][4] = {};
    for (int k0 = 0; k0 < HD; k0 += 16) {
        float4 av = *(const float4*)(Ap + k0);
        float4 b1 = *(const float4*)(B1p + k0);
        float4 b3 = *(const float4*)(B3p + k0);
        As [la_k + 0][la_r] = av.x; As [la_k + 1][la_r] = av.y; As [la_k + 2][la_r] = av.z; As [la_k + 3][la_r] = av.w;
        B1s[la_k + 0][la_r] = b1.x; B1s[la_k + 1][la_r] = b1.y; B1s[la_k + 2][la_r] = b1.z; B1s[la_k + 3][la_r] = b1.w;
        B3s[la_k + 0][la_r] = b3.x; B3s[la_k + 1][la_r] = b3.y; B3s[la_k + 2][la_r] = b3.z; B3s[la_k + 3][la_r] = b3.w;
        __syncthreads();
#pragma unroll
        for (int kk = 0; kk < 16; kk++) {
            float4 af  = *(const float4*)&As [kk][ty * 4];
            float4 b1f = *(const float4*)&B1s[kk][tx * 4];
            float4 b3f = *(const float4*)&B3s[kk][tx * 4];
            float avr[4] = {af.x, af.y, af.z, af.w};
            float b1r[4] = {b1f.x, b1f.y, b1f.z, b1f.w};
            float b3r[4] = {b3f.x, b3f.y, b3f.z, b3f.w};
#pragma unroll
            for (int i = 0; i < 4; i++)
#pragma unroll
                for (int j = 0; j < 4; j++) {
                    acc1[i][j] += avr[i] * b1r[j];
                    acc3[i][j] += avr[i] * b3r[j];
                }
        }
        __syncthreads();
    }
#pragma unroll
    for (int i = 0; i < 4; i++) {
        int pos = rowBase + ty * 4 + i;
        if (pos < cnt) {
            float vals[4];
#pragma unroll
            for (int j = 0; j < 4; j++) {
                float gv = acc1[i][j];
                float sv = gv / (1.f + __expf(-gv));   // silu
                vals[j] = sv * acc3[i][j];
            }
            *(float4*)(g_hg + ((size_t)e * TOK + pos) * FF + colBase + tx * 4) =
                make_float4(vals[0], vals[1], vals[2], vals[3]);
        }
    }
}

// ---------------- MoE down: out += we * (hg @ W2^T), scatter by token ----------------
__global__ void moe_down_kernel(const float* __restrict__ W2, float* __restrict__ out) {
    int e = blockIdx.z;
    int cnt = g_cnt[e];
    int rowBase = blockIdx.y * 64;
    if (rowBase >= cnt) return;
    int colBase = blockIdx.x * 64;
    __shared__ float As[16][68], Bs[16][68];
    int tid = threadIdx.x;
    int tx = tid & 15, ty = tid >> 4;
    int la_r = tid >> 2, la_k = (tid & 3) * 4;
    const float* Ap = g_hg + ((size_t)e * TOK + rowBase + la_r) * FF + la_k;
    const float* Bp = W2 + (size_t)e * HD * FF + (size_t)(colBase + la_r) * FF + la_k;
    float acc[4][4] = {};
    for (int k0 = 0; k0 < FF; k0 += 16) {
        float4 av = *(const float4*)(Ap + k0);
        float4 bv = *(const float4*)(Bp + k0);
        As[la_k + 0][la_r] = av.x; As[la_k + 1][la_r] = av.y; As[la_k + 2][la_r] = av.z; As[la_k + 3][la_r] = av.w;
        Bs[la_k + 0][la_r] = bv.x; Bs[la_k + 1][la_r] = bv.y; Bs[la_k + 2][la_r] = bv.z; Bs[la_k + 3][la_r] = bv.w;
        __syncthreads();
#pragma unroll
        for (int kk = 0; kk < 16; kk++) {
            float4 af = *(const float4*)&As[kk][ty * 4];
            float4 bf = *(const float4*)&Bs[kk][tx * 4];
            float avr[4] = {af.x, af.y, af.z, af.w};
            float bvr[4] = {bf.x, bf.y, bf.z, bf.w};
#pragma unroll
            for (int i = 0; i < 4; i++)
#pragma unroll
                for (int j = 0; j < 4; j++)
                    acc[i][j] += avr[i] * bvr[j];
        }
        __syncthreads();
    }
#pragma unroll
    for (int i = 0; i < 4; i++) {
        int pos = rowBase + ty * 4 + i;
        if (pos < cnt) {
            int token = g_idx[e * TOK + pos];
            float w = g_we[token * NEXP + e];
            float* dst = out + (size_t)token * HD + colBase + tx * 4;
#pragma unroll
            for (int j = 0; j < 4; j++)
                atomicAdd(dst + j, w * acc[i][j]);
        }
    }
}

// ---------------- residual copy into out ----------------
__global__ void copy_kernel(float* __restrict__ out) {
    int i = blockIdx.x * 256 + threadIdx.x;
    *(float4*)(out + (size_t)i * 4) = *(const float4*)(g_x1 + (size_t)i * 4);
}

// ---------------- lb loss ----------------
__global__ void lb_kernel(float* __restrict__ out) {
    if (threadIdx.x == 0) {
        float s = 0.f;
#pragma unroll
        for (int e = 0; e < NEXP; e++) s += g_usage[e] * g_usage[e];
        out[(size_t)TOK * HD] = (float)NEXP * s;
    }
}

// ---------------- launch ----------------
extern "C" void kernel_launch(void* const* d_in, const int* in_sizes, int n_in,
                              void* d_out, int out_size) {
    const float* x    = (const float*)d_in[0];
    const float* Wq   = (const float*)d_in[1];
    const float* Wk   = (const float*)d_in[2];
    const float* Wv   = (const float*)d_in[3];
    const float* Wo   = (const float*)d_in[4];
    const float* ln1g = (const float*)d_in[5];
    const float* ln1b = (const float*)d_in[6];
    const float* ln2g = (const float*)d_in[7];
    const float* ln2b = (const float*)d_in[8];
    const float* Wr   = (const float*)d_in[9];
    const float* W1   = (const float*)d_in[10];
    const float* W2   = (const float*)d_in[11];
    const float* W3   = (const float*)d_in[12];
    float* out = (float*)d_out;

    float *ph1, *pq, *pk, *pv, *pattn, *px1, *ph2;
    cudaGetSymbolAddress((void**)&ph1,   g_h1);
    cudaGetSymbolAddress((void**)&pq,    g_q);
    cudaGetSymbolAddress((void**)&pk,    g_k);
    cudaGetSymbolAddress((void**)&pv,    g_v);
    cudaGetSymbolAddress((void**)&pattn, g_attn);
    cudaGetSymbolAddress((void**)&px1,   g_x1);
    cudaGetSymbolAddress((void**)&ph2,   g_h2);

    cudaFuncSetAttribute(attn_kernel, cudaFuncAttributeMaxDynamicSharedMemorySize,
                         3 * 64 * 68 * (int)sizeof(float));

    init_kernel<<<1, 32>>>();
    // x -> ln1 -> h1
    ln_kernel<<<TOK, 256>>>(x, ln1g, ln1b, ph1);
    // q,k,v projections
    gemm_nt_kernel<false><<<dim3(HD / 64, TOK / 64), 256>>>(ph1, Wq, nullptr, pq, HD, HD);
    gemm_nt_kernel<false><<<dim3(HD / 64, TOK / 64), 256>>>(ph1, Wk, nullptr, pk, HD, HD);
    gemm_nt_kernel<false><<<dim3(HD / 64, TOK / 64), 256>>>(ph1, Wv, nullptr, pv, HD, HD);
    // attention
    attn_kernel<<<dim3(SEQ / 64, 2 * NHEAD), 256, 3 * 64 * 68 * sizeof(float)>>>();
    // x1 = x + attn @ Wo^T
    gemm_nt_kernel<true><<<dim3(HD / 64, TOK / 64), 256>>>(pattn, Wo, x, px1, HD, HD);
    // ln2
    ln_kernel<<<TOK, 256>>>(px1, ln2g, ln2b, ph2);
    // router (logits, top-2 dispatch, usage)
    router_kernel<<<TOK / 8, 256>>>(Wr);
    // out = x1 (residual base)
    copy_kernel<<<TOK * HD / 1024, 256>>>(out);
    // sparse expert FFN
    moe_up_kernel<<<dim3(FF / 64, TOK / 64, NEXP), 256>>>(W1, W3);
    moe_down_kernel<<<dim3(HD / 64, TOK / 64, NEXP), 256>>>(W2, out);
    // lb loss scalar
    if ((long long)out_size >= (long long)TOK * HD + 1)
        lb_kernel<<<1, 32>>>(out);
}

// round 3
// speedup vs baseline: 2.9334x; 2.9334x over previous
#include <cuda_runtime.h>
#include <math.h>
#include <stdint.h>

#define TOK   2048
#define HD    1024
#define NHEAD 16
#define DH    64
#define NEXP  8
#define FF    4096
#define SEQ   1024

// ---------------- scratch ----------------
__device__ float g_h1[TOK * HD];
__device__ float g_q [TOK * HD];
__device__ float g_k [TOK * HD];
__device__ float g_v [TOK * HD];
__device__ float g_attn[TOK * HD];
__device__ float g_x1[TOK * HD];
__device__ float g_h2[TOK * HD];
__device__ float g_we[TOK * NEXP];
__device__ float g_usage[NEXP];
__device__ int   g_cnt[NEXP];
__device__ int   g_idx[NEXP * TOK];
__device__ float g_hgA[(size_t)NEXP * TOK * FF];
__device__ float g_hgB[(size_t)NEXP * TOK * FF];

// ---------------- helpers ----------------
__device__ __forceinline__ uint32_t smem_u32(const void* p) {
    uint32_t a;
    asm("{ .reg .u64 t; cvta.to.shared.u64 t, %1; cvt.u32.u64 %0, t; }" : "=r"(a) : "l"(p));
    return a;
}
__device__ __forceinline__ uint32_t f2tf(float f) {
    uint32_t u;
    asm("cvt.rna.tf32.f32 %0, %1;" : "=r"(u) : "f"(f));
    return u;
}
__device__ __forceinline__ void mma8(float* c, const uint32_t* a, const uint32_t* b) {
    asm volatile(
        "mma.sync.aligned.m16n8k8.row.col.f32.tf32.tf32.f32 "
        "{%0,%1,%2,%3}, {%4,%5,%6,%7}, {%8,%9}, {%0,%1,%2,%3};"
        : "+f"(c[0]), "+f"(c[1]), "+f"(c[2]), "+f"(c[3])
        : "r"(a[0]), "r"(a[1]), "r"(a[2]), "r"(a[3]), "r"(b[0]), "r"(b[1]));
}
__device__ __forceinline__ void cp16(uint32_t dst, const float* src) {
    asm volatile("cp.async.cg.shared.global [%0], [%1], 16;" :: "r"(dst), "l"(src));
}
#define CP_COMMIT() asm volatile("cp.async.commit_group;" ::: "memory")
#define CP_WAIT0()  asm volatile("cp.async.wait_group 0;" ::: "memory")

// smem layout (bytes): As[2][128][36] | Bs[2][128][36] | Aptr[128]
#define OFF_B   36864
#define OFF_PTR 73728
#define SMEM_GEMM 75264
#define LDW 36

// issue one 128x32 A tile + 128x32 B tile stage via cp.async
__device__ __forceinline__ void issue_stage(uint32_t sb, const float* const* Aptr,
                                            const float* Bbase, size_t strideB,
                                            int k0, int s, int tid) {
#pragma unroll
    for (int i = 0; i < 4; i++) {
        int idx = tid + i * 256;
        int row = idx >> 3, col = (idx & 7) * 4;
        cp16(sb + (uint32_t)(((s * 128 + row) * LDW + col) * 4), Aptr[row] + k0 + col);
        cp16(sb + OFF_B + (uint32_t)(((s * 128 + row) * LDW + col) * 4),
             Bbase + (size_t)row * strideB + k0 + col);
    }
}

// compute 128x128x32 on one stage buffer
__device__ __forceinline__ void compute_tile(const float* As, const float* Bs,
                                             int warpM, int warpN, int g, int tg,
                                             float acc[4][4][4]) {
#pragma unroll
    for (int ks = 0; ks < 4; ks++) {
        int kk = ks * 8;
        uint32_t a[4][4];
#pragma unroll
        for (int mt = 0; mt < 4; mt++) {
            const float* p = As + (warpM + mt * 16) * LDW + kk;
            a[mt][0] = f2tf(p[g * LDW + tg]);
            a[mt][1] = f2tf(p[(g + 8) * LDW + tg]);
            a[mt][2] = f2tf(p[g * LDW + tg + 4]);
            a[mt][3] = f2tf(p[(g + 8) * LDW + tg + 4]);
        }
        uint32_t b[4][2];
#pragma unroll
        for (int nt = 0; nt < 4; nt++) {
            const float* p = Bs + (warpN + nt * 8 + g) * LDW + kk;
            b[nt][0] = f2tf(p[tg]);
            b[nt][1] = f2tf(p[tg + 4]);
        }
#pragma unroll
        for (int mt = 0; mt < 4; mt++)
#pragma unroll
            for (int nt = 0; nt < 4; nt++)
                mma8(acc[mt][nt], a[mt], b[nt]);
    }
}

// ---------------- init ----------------
__global__ void init_kernel() {
    int t = threadIdx.x;
    if (t < NEXP) { g_cnt[t] = 0; g_usage[t] = 0.f; }
}

// ---------------- layernorm ----------------
__global__ void ln_kernel(const float* __restrict__ x, const float* __restrict__ g,
                          const float* __restrict__ b, float* __restrict__ y) {
    __shared__ float red[256];
    int row = blockIdx.x;
    const float* xr = x + (size_t)row * HD;
    float s = 0.f;
    for (int i = threadIdx.x; i < HD; i += 256) s += xr[i];
    red[threadIdx.x] = s; __syncthreads();
    for (int o = 128; o > 0; o >>= 1) {
        if (threadIdx.x < o) red[threadIdx.x] += red[threadIdx.x + o];
        __syncthreads();
    }
    float mu = red[0] * (1.f / HD);
    __syncthreads();
    float v = 0.f;
    for (int i = threadIdx.x; i < HD; i += 256) { float d = xr[i] - mu; v += d * d; }
    red[threadIdx.x] = v; __syncthreads();
    for (int o = 128; o > 0; o >>= 1) {
        if (threadIdx.x < o) red[threadIdx.x] += red[threadIdx.x + o];
        __syncthreads();
    }
    float rstd = rsqrtf(red[0] * (1.f / HD) + 1e-5f);
    float* yr = y + (size_t)row * HD;
    for (int i = threadIdx.x; i < HD; i += 256)
        yr[i] = (xr[i] - mu) * rstd * g[i] + b[i];
}

// ---------------- QKV projections (tf32 mma) ----------------
__global__ __launch_bounds__(256) void qkv_mma(const float* __restrict__ Wq,
                                               const float* __restrict__ Wk,
                                               const float* __restrict__ Wv) {
    extern __shared__ char sm[];
    float* As = (float*)sm;
    float* Bs = (float*)(sm + OFF_B);
    const float** Aptr = (const float**)(sm + OFF_PTR);
    int tid = threadIdx.x, wid = tid >> 5, lane = tid & 31;
    int g = lane >> 2, tg = lane & 3;
    int warpM = (wid >> 2) * 64, warpN = (wid & 3) * 32;
    const float* W = blockIdx.z == 0 ? Wq : (blockIdx.z == 1 ? Wk : Wv);
    float* C = blockIdx.z == 0 ? g_q : (blockIdx.z == 1 ? g_k : g_v);
    int rowBase = blockIdx.y * 128, colBase = blockIdx.x * 128;
    if (tid < 128) Aptr[tid] = g_h1 + (size_t)(rowBase + tid) * HD;
    __syncthreads();
    const float* Bbase = W + (size_t)colBase * HD;
    uint32_t sb = smem_u32(sm);
    float acc[4][4][4] = {};
    issue_stage(sb, Aptr, Bbase, HD, 0, 0, tid); CP_COMMIT();
    for (int kb = 0; kb < HD / 32; kb++) {
        CP_WAIT0(); __syncthreads();
        if (kb + 1 < HD / 32) { issue_stage(sb, Aptr, Bbase, HD, (kb + 1) * 32, (kb + 1) & 1, tid); CP_COMMIT(); }
        compute_tile(As + (kb & 1) * 128 * LDW, Bs + (kb & 1) * 128 * LDW, warpM, warpN, g, tg, acc);
        __syncthreads();
    }
#pragma unroll
    for (int mt = 0; mt < 4; mt++)
#pragma unroll
        for (int nt = 0; nt < 4; nt++) {
            int r0 = rowBase + warpM + mt * 16 + g;
            int c0 = colBase + warpN + nt * 8 + 2 * tg;
            *(float2*)(C + (size_t)r0 * HD + c0) = make_float2(acc[mt][nt][0], acc[mt][nt][1]);
            *(float2*)(C + (size_t)(r0 + 8) * HD + c0) = make_float2(acc[mt][nt][2], acc[mt][nt][3]);
        }
}

// ---------------- O projection + residual ----------------
__global__ __launch_bounds__(256) void oproj_mma(const float* __restrict__ Wo,
                                                 const float* __restrict__ xres) {
    extern __shared__ char sm[];
    float* As = (float*)sm;
    float* Bs = (float*)(sm + OFF_B);
    const float** Aptr = (const float**)(sm + OFF_PTR);
    int tid = threadIdx.x, wid = tid >> 5, lane = tid & 31;
    int g = lane >> 2, tg = lane & 3;
    int warpM = (wid >> 2) * 64, warpN = (wid & 3) * 32;
    int rowBase = blockIdx.y * 128, colBase = blockIdx.x * 128;
    if (tid < 128) Aptr[tid] = g_attn + (size_t)(rowBase + tid) * HD;
    __syncthreads();
    const float* Bbase = Wo + (size_t)colBase * HD;
    uint32_t sb = smem_u32(sm);
    float acc[4][4][4] = {};
    issue_stage(sb, Aptr, Bbase, HD, 0, 0, tid); CP_COMMIT();
    for (int kb = 0; kb < HD / 32; kb++) {
        CP_WAIT0(); __syncthreads();
        if (kb + 1 < HD / 32) { issue_stage(sb, Aptr, Bbase, HD, (kb + 1) * 32, (kb + 1) & 1, tid); CP_COMMIT(); }
        compute_tile(As + (kb & 1) * 128 * LDW, Bs + (kb & 1) * 128 * LDW, warpM, warpN, g, tg, acc);
        __syncthreads();
    }
#pragma unroll
    for (int mt = 0; mt < 4; mt++)
#pragma unroll
        for (int nt = 0; nt < 4; nt++) {
            int r0 = rowBase + warpM + mt * 16 + g;
            int c0 = colBase + warpN + nt * 8 + 2 * tg;
            float2 a = *(const float2*)(xres + (size_t)r0 * HD + c0);
            float2 b = *(const float2*)(xres + (size_t)(r0 + 8) * HD + c0);
            *(float2*)(g_x1 + (size_t)r0 * HD + c0) = make_float2(acc[mt][nt][0] + a.x, acc[mt][nt][1] + a.y);
            *(float2*)(g_x1 + (size_t)(r0 + 8) * HD + c0) = make_float2(acc[mt][nt][2] + b.x, acc[mt][nt][3] + b.y);
        }
}

// ---------------- flash attention (causal, fp32 SIMT) ----------------
__global__ void attn_kernel() {
    extern __shared__ float smf[];
    float (*Qs)[68]  = (float(*)[68])smf;
    float (*KVs)[68] = (float(*)[68])(smf + 64 * 68);
    float (*Ps)[68]  = (float(*)[68])(smf + 2 * 64 * 68);
    int qt = blockIdx.x, bh = blockIdx.y;
    int b = bh >> 4, h = bh & 15;
    int tid = threadIdx.x;
    int tx = tid & 15, ty = tid >> 4;
    int lr = tid >> 2, lk = (tid & 3) * 4;
    {
        const float* qp = g_q + (size_t)(b * SEQ + qt * 64 + lr) * HD + h * DH;
#pragma unroll
        for (int p = 0; p < 4; p++) {
            float4 v = *(const float4*)(qp + lk + p * 16);
            int d0 = lk + p * 16;
            Qs[d0 + 0][lr] = v.x; Qs[d0 + 1][lr] = v.y;
            Qs[d0 + 2][lr] = v.z; Qs[d0 + 3][lr] = v.w;
        }
    }
    float m_i[4], l_i[4], outAcc[4][4];
#pragma unroll
    for (int i = 0; i < 4; i++) {
        m_i[i] = -1e30f; l_i[i] = 0.f;
#pragma unroll
        for (int j = 0; j < 4; j++) outAcc[i][j] = 0.f;
    }
    __syncthreads();
    for (int kt = 0; kt <= qt; kt++) {
        {
            const float* kp = g_k + (size_t)(b * SEQ + kt * 64 + lr) * HD + h * DH;
#pragma unroll
            for (int p = 0; p < 4; p++) {
                float4 v = *(const float4*)(kp + lk + p * 16);
                int d0 = lk + p * 16;
                KVs[d0 + 0][lr] = v.x; KVs[d0 + 1][lr] = v.y;
                KVs[d0 + 2][lr] = v.z; KVs[d0 + 3][lr] = v.w;
            }
        }
        __syncthreads();
        float s[4][4] = {};
#pragma unroll 16
        for (int kk = 0; kk < 64; kk++) {
            float4 af = *(const float4*)&Qs[kk][ty * 4];
            float4 bf = *(const float4*)&KVs[kk][tx * 4];
            float avr[4] = {af.x, af.y, af.z, af.w};
            float bvr[4] = {bf.x, bf.y, bf.z, bf.w};
#pragma unroll
            for (int i = 0; i < 4; i++)
#pragma unroll
                for (int j = 0; j < 4; j++)
                    s[i][j] += avr[i] * bvr[j];
        }
        if (kt == qt) {
#pragma unroll
            for (int i = 0; i < 4; i++)
#pragma unroll
                for (int j = 0; j < 4; j++) {
                    int rr = ty * 4 + i, cc = tx * 4 + j;
                    s[i][j] = (cc > rr) ? -1e30f : s[i][j] * 0.125f;
                }
        } else {
#pragma unroll
            for (int i = 0; i < 4; i++)
#pragma unroll
                for (int j = 0; j < 4; j++) s[i][j] *= 0.125f;
        }
#pragma unroll
        for (int i = 0; i < 4; i++) {
            float rmax = fmaxf(fmaxf(s[i][0], s[i][1]), fmaxf(s[i][2], s[i][3]));
#pragma unroll
            for (int o = 8; o > 0; o >>= 1)
                rmax = fmaxf(rmax, __shfl_xor_sync(0xffffffffu, rmax, o));
            float mnew = fmaxf(m_i[i], rmax);
            float rsum = 0.f;
#pragma unroll
            for (int j = 0; j < 4; j++) { float p = __expf(s[i][j] - mnew); s[i][j] = p; rsum += p; }
#pragma unroll
            for (int o = 8; o > 0; o >>= 1)
                rsum += __shfl_xor_sync(0xffffffffu, rsum, o);
            float alpha = __expf(m_i[i] - mnew);
            l_i[i] = l_i[i] * alpha + rsum;
            m_i[i] = mnew;
#pragma unroll
            for (int j = 0; j < 4; j++) outAcc[i][j] *= alpha;
            *(float4*)&Ps[ty * 4 + i][tx * 4] = make_float4(s[i][0], s[i][1], s[i][2], s[i][3]);
        }
        __syncthreads();
        {
            const float* vp = g_v + (size_t)(b * SEQ + kt * 64 + lr) * HD + h * DH;
#pragma unroll
            for (int p = 0; p < 4; p++)
                *(float4*)&KVs[lr][lk + p * 16] = *(const float4*)(vp + lk + p * 16);
        }
        __syncthreads();
#pragma unroll 16
        for (int jj = 0; jj < 64; jj++) {
            float4 bf = *(const float4*)&KVs[jj][tx * 4];
            float p0 = Ps[ty * 4 + 0][jj], p1 = Ps[ty * 4 + 1][jj];
            float p2 = Ps[ty * 4 + 2][jj], p3 = Ps[ty * 4 + 3][jj];
            outAcc[0][0] += p0 * bf.x; outAcc[0][1] += p0 * bf.y; outAcc[0][2] += p0 * bf.z; outAcc[0][3] += p0 * bf.w;
            outAcc[1][0] += p1 * bf.x; outAcc[1][1] += p1 * bf.y; outAcc[1][2] += p1 * bf.z; outAcc[1][3] += p1 * bf.w;
            outAcc[2][0] += p2 * bf.x; outAcc[2][1] += p2 * bf.y; outAcc[2][2] += p2 * bf.z; outAcc[2][3] += p2 * bf.w;
            outAcc[3][0] += p3 * bf.x; outAcc[3][1] += p3 * bf.y; outAcc[3][2] += p3 * bf.z; outAcc[3][3] += p3 * bf.w;
        }
        __syncthreads();
    }
#pragma unroll
    for (int i = 0; i < 4; i++) {
        float inv = 1.f / l_i[i];
        int q = qt * 64 + ty * 4 + i;
        *(float4*)(g_attn + (size_t)(b * SEQ + q) * HD + h * DH + tx * 4) =
            make_float4(outAcc[i][0] * inv, outAcc[i][1] * inv, outAcc[i][2] * inv, outAcc[i][3] * inv);
    }
}

// ---------------- router ----------------
__global__ void router_kernel(const float* __restrict__ Wr) {
    int gwarp = (blockIdx.x * blockDim.x + threadIdx.x) >> 5;
    int lane = threadIdx.x & 31;
    if (gwarp >= TOK) return;
    const float* xr = g_h2 + (size_t)gwarp * HD;
    float acc[NEXP] = {};
    for (int i = lane; i < HD; i += 32) {
        float xv = xr[i];
#pragma unroll
        for (int e = 0; e < NEXP; e++) acc[e] += xv * Wr[e * HD + i];
    }
#pragma unroll
    for (int e = 0; e < NEXP; e++)
#pragma unroll
        for (int o = 16; o > 0; o >>= 1)
            acc[e] += __shfl_xor_sync(0xffffffffu, acc[e], o);
    if (lane == 0) {
        float mx = acc[0];
#pragma unroll
        for (int e = 1; e < NEXP; e++) mx = fmaxf(mx, acc[e]);
        float p[NEXP], se = 0.f;
#pragma unroll
        for (int e = 0; e < NEXP; e++) { p[e] = __expf(acc[e] - mx); se += p[e]; }
        float inv = 1.f / (se * (float)TOK);
#pragma unroll
        for (int e = 0; e < NEXP; e++) atomicAdd(&g_usage[e], p[e] * inv);
        int i0 = 0;
#pragma unroll
        for (int e = 1; e < NEXP; e++) if (acc[e] > acc[i0]) i0 = e;
        int i1 = (i0 == 0) ? 1 : 0;
#pragma unroll
        for (int e = 0; e < NEXP; e++) if (e != i0 && acc[e] > acc[i1]) i1 = e;
        float l0 = acc[i0], l1 = acc[i1];
        float m2 = fmaxf(l0, l1);
        float e0 = __expf(l0 - m2), e1 = __expf(l1 - m2);
        float s2 = e0 + e1;
        g_we[gwarp * NEXP + i0] = e0 / s2;
        g_we[gwarp * NEXP + i1] = e1 / s2;
        int p0 = atomicAdd(&g_cnt[i0], 1); g_idx[i0 * TOK + p0] = gwarp;
        int p1 = atomicAdd(&g_cnt[i1], 1); g_idx[i1 * TOK + p1] = gwarp;
    }
}

// ---------------- MoE up (raw GEMMs into g_hgA / g_hgB) ----------------
__global__ __launch_bounds__(256) void moe_up_mma(const float* __restrict__ W1,
                                                  const float* __restrict__ W3) {
    extern __shared__ char sm[];
    int e = blockIdx.z;
    int cnt = g_cnt[e];
    int rowBase = blockIdx.y * 128;
    if (rowBase >= cnt) return;
    int half = blockIdx.x >> 5;
    int colBase = (blockIdx.x & 31) * 128;
    const float* W = half ? W3 : W1;
    float* dstb = half ? g_hgB : g_hgA;
    float* As = (float*)sm;
    float* Bs = (float*)(sm + OFF_B);
    const float** Aptr = (const float**)(sm + OFF_PTR);
    int tid = threadIdx.x, wid = tid >> 5, lane = tid & 31;
    int g = lane >> 2, tg = lane & 3;
    int warpM = (wid >> 2) * 64, warpN = (wid & 3) * 32;
    if (tid < 128) {
        int p = rowBase + tid;
        Aptr[tid] = g_h2 + (size_t)g_idx[e * TOK + (p < cnt ? p : cnt - 1)] * HD;
    }
    __syncthreads();
    const float* Bbase = W + (size_t)e * FF * HD + (size_t)colBase * HD;
    uint32_t sb = smem_u32(sm);
    float acc[4][4][4] = {};
    issue_stage(sb, Aptr, Bbase, HD, 0, 0, tid); CP_COMMIT();
    for (int kb = 0; kb < HD / 32; kb++) {
        CP_WAIT0(); __syncthreads();
        if (kb + 1 < HD / 32) { issue_stage(sb, Aptr, Bbase, HD, (kb + 1) * 32, (kb + 1) & 1, tid); CP_COMMIT(); }
        compute_tile(As + (kb & 1) * 128 * LDW, Bs + (kb & 1) * 128 * LDW, warpM, warpN, g, tg, acc);
        __syncthreads();
    }
#pragma unroll
    for (int mt = 0; mt < 4; mt++)
#pragma unroll
        for (int nt = 0; nt < 4; nt++) {
            int p0 = rowBase + warpM + mt * 16 + g;
            int c0 = colBase + warpN + nt * 8 + 2 * tg;
            if (p0 < cnt)
                *(float2*)(dstb + ((size_t)e * TOK + p0) * FF + c0) =
                    make_float2(acc[mt][nt][0], acc[mt][nt][1]);
            if (p0 + 8 < cnt)
                *(float2*)(dstb + ((size_t)e * TOK + p0 + 8) * FF + c0) =
                    make_float2(acc[mt][nt][2], acc[mt][nt][3]);
        }
}

// ---------------- silu * mul ----------------
__global__ void silu_mul_kernel() {
    int e = blockIdx.y;
    int cnt = g_cnt[e];
    int pos = blockIdx.x;
    if (pos >= cnt) return;
    size_t off = ((size_t)e * TOK + pos) * FF;
    for (int i = threadIdx.x; i < FF / 4; i += 256) {
        float4 a = *(const float4*)(g_hgA + off + (size_t)i * 4);
        float4 b = *(const float4*)(g_hgB + off + (size_t)i * 4);
        a.x = a.x / (1.f + __expf(-a.x)) * b.x;
        a.y = a.y / (1.f + __expf(-a.y)) * b.y;
        a.z = a.z / (1.f + __expf(-a.z)) * b.z;
        a.w = a.w / (1.f + __expf(-a.w)) * b.w;
        *(float4*)(g_hgA + off + (size_t)i * 4) = a;
    }
}

// ---------------- MoE down (scatter-atomic) ----------------
__global__ __launch_bounds__(256) void moe_down_mma(const float* __restrict__ W2,
                                                    float* __restrict__ out) {
    extern __shared__ char sm[];
    int e = blockIdx.z;
    int cnt = g_cnt[e];
    int rowBase = blockIdx.y * 128;
    if (rowBase >= cnt) return;
    int colBase = blockIdx.x * 128;
    float* As = (float*)sm;
    float* Bs = (float*)(sm + OFF_B);
    const float** Aptr = (const float**)(sm + OFF_PTR);
    int tid = threadIdx.x, wid = tid >> 5, lane = tid & 31;
    int g = lane >> 2, tg = lane & 3;
    int warpM = (wid >> 2) * 64, warpN = (wid & 3) * 32;
    if (tid < 128)
        Aptr[tid] = g_hgA + ((size_t)e * TOK + rowBase + tid) * FF;
    __syncthreads();
    const float* Bbase = W2 + (size_t)e * HD * FF + (size_t)colBase * FF;
    uint32_t sb = smem_u32(sm);
    float acc[4][4][4] = {};
    issue_stage(sb, Aptr, Bbase, FF, 0, 0, tid); CP_COMMIT();
    for (int kb = 0; kb < FF / 32; kb++) {
        CP_WAIT0(); __syncthreads();
        if (kb + 1 < FF / 32) { issue_stage(sb, Aptr, Bbase, FF, (kb + 1) * 32, (kb + 1) & 1, tid); CP_COMMIT(); }
        compute_tile(As + (kb & 1) * 128 * LDW, Bs + (kb & 1) * 128 * LDW, warpM, warpN, g, tg, acc);
        __syncthreads();
    }
#pragma unroll
    for (int mt = 0; mt < 4; mt++) {
        int p0 = rowBase + warpM + mt * 16 + g;
        int p1 = p0 + 8;
        int t0 = 0, t1 = 0; float w0 = 0.f, w1 = 0.f;
        if (p0 < cnt) { t0 = g_idx[e * TOK + p0]; w0 = g_we[t0 * NEXP + e]; }
        if (p1 < cnt) { t1 = g_idx[e * TOK + p1]; w1 = g_we[t1 * NEXP + e]; }
#pragma unroll
        for (int nt = 0; nt < 4; nt++) {
            int c0 = colBase + warpN + nt * 8 + 2 * tg;
            if (p0 < cnt) {
                atomicAdd(out + (size_t)t0 * HD + c0,     w0 * acc[mt][nt][0]);
                atomicAdd(out + (size_t)t0 * HD + c0 + 1, w0 * acc[mt][nt][1]);
            }
            if (p1 < cnt) {
                atomicAdd(out + (size_t)t1 * HD + c0,     w1 * acc[mt][nt][2]);
                atomicAdd(out + (size_t)t1 * HD + c0 + 1, w1 * acc[mt][nt][3]);
            }
        }
    }
}

// ---------------- residual copy / lb ----------------
__global__ void copy_kernel(float* __restrict__ out) {
    int i = blockIdx.x * 256 + threadIdx.x;
    *(float4*)(out + (size_t)i * 4) = *(const float4*)(g_x1 + (size_t)i * 4);
}
__global__ void lb_kernel(float* __restrict__ out) {
    if (threadIdx.x == 0) {
        float s = 0.f;
#pragma unroll
        for (int e = 0; e < NEXP; e++) s += g_usage[e] * g_usage[e];
        out[(size_t)TOK * HD] = (float)NEXP * s;
    }
}

// ---------------- launch ----------------
extern "C" void kernel_launch(void* const* d_in, const int* in_sizes, int n_in,
                              void* d_out, int out_size) {
    const float* x    = (const float*)d_in[0];
    const float* Wq   = (const float*)d_in[1];
    const float* Wk   = (const float*)d_in[2];
    const float* Wv   = (const float*)d_in[3];
    const float* Wo   = (const float*)d_in[4];
    const float* ln1g = (const float*)d_in[5];
    const float* ln1b = (const float*)d_in[6];
    const float* ln2g = (const float*)d_in[7];
    const float* ln2b = (const float*)d_in[8];
    const float* Wr   = (const float*)d_in[9];
    const float* W1   = (const float*)d_in[10];
    const float* W2   = (const float*)d_in[11];
    const float* W3   = (const float*)d_in[12];
    float* out = (float*)d_out;

    float *ph1, *px1, *ph2;
    cudaGetSymbolAddress((void**)&ph1, g_h1);
    cudaGetSymbolAddress((void**)&px1, g_x1);
    cudaGetSymbolAddress((void**)&ph2, g_h2);

    cudaFuncSetAttribute(qkv_mma,      cudaFuncAttributeMaxDynamicSharedMemorySize, SMEM_GEMM);
    cudaFuncSetAttribute(oproj_mma,    cudaFuncAttributeMaxDynamicSharedMemorySize, SMEM_GEMM);
    cudaFuncSetAttribute(moe_up_mma,   cudaFuncAttributeMaxDynamicSharedMemorySize, SMEM_GEMM);
    cudaFuncSetAttribute(moe_down_mma, cudaFuncAttributeMaxDynamicSharedMemorySize, SMEM_GEMM);
    cudaFuncSetAttribute(attn_kernel,  cudaFuncAttributeMaxDynamicSharedMemorySize,
                         3 * 64 * 68 * (int)sizeof(float));

    init_kernel<<<1, 32>>>();
    ln_kernel<<<TOK, 256>>>(x, ln1g, ln1b, ph1);
    qkv_mma<<<dim3(HD / 128, TOK / 128, 3), 256, SMEM_GEMM>>>(Wq, Wk, Wv);
    attn_kernel<<<dim3(SEQ / 64, 2 * NHEAD), 256, 3 * 64 * 68 * sizeof(float)>>>();
    oproj_mma<<<dim3(HD / 128, TOK / 128), 256, SMEM_GEMM>>>(Wo, x);
    ln_kernel<<<TOK, 256>>>(px1, ln2g, ln2b, ph2);
    router_kernel<<<TOK / 8, 256>>>(Wr);
    copy_kernel<<<TOK * HD / 1024, 256>>>(out);
    moe_up_mma<<<dim3(2 * FF / 128, TOK / 128, NEXP), 256, SMEM_GEMM>>>(W1, W3);
    silu_mul_kernel<<<dim3(TOK, NEXP), 256>>>();
    moe_down_mma<<<dim3(HD / 128, TOK / 128, NEXP), 256, SMEM_GEMM>>>(W2, out);
    if ((long long)out_size >= (long long)TOK * HD + 1)
        lb_kernel<<<1, 32>>>(out);
}

// round 5
// speedup vs baseline: 3.7083x; 1.2642x over previous
#include <cuda_runtime.h>
#include <math.h>
#include <stdint.h>

#define TOK   2048
#define HD    1024
#define NHEAD 16
#define DH    64
#define NEXP  8
#define FF    4096
#define SEQ   1024

// ---------------- scratch ----------------
__device__ float g_h1[TOK * HD];
__device__ float g_q [TOK * HD];
__device__ float g_k [TOK * HD];
__device__ float g_v [TOK * HD];
__device__ float g_attn[TOK * HD];
__device__ float g_x1[TOK * HD];
__device__ float g_h2[TOK * HD];
__device__ float g_we[TOK * NEXP];
__device__ float g_usage[NEXP];
__device__ int   g_cnt[NEXP];
__device__ int   g_idx[NEXP * TOK];
__device__ float g_hgA[(size_t)NEXP * TOK * FF];
__device__ float g_hgB[(size_t)NEXP * TOK * FF];

// ---------------- helpers ----------------
__device__ __forceinline__ uint32_t smem_u32(const void* p) {
    uint32_t a;
    asm("{ .reg .u64 t; cvta.to.shared.u64 t, %1; cvt.u32.u64 %0, t; }" : "=r"(a) : "l"(p));
    return a;
}
__device__ __forceinline__ void mma8(float* c, const uint32_t* a, const uint32_t* b) {
    asm volatile(
        "mma.sync.aligned.m16n8k8.row.col.f32.tf32.tf32.f32 "
        "{%0,%1,%2,%3}, {%4,%5,%6,%7}, {%8,%9}, {%0,%1,%2,%3};"
        : "+f"(c[0]), "+f"(c[1]), "+f"(c[2]), "+f"(c[3])
        : "r"(a[0]), "r"(a[1]), "r"(a[2]), "r"(a[3]), "r"(b[0]), "r"(b[1]));
}
__device__ __forceinline__ void cp16(uint32_t dst, const float* src) {
    asm volatile("cp.async.cg.shared.global [%0], [%1], 16;" :: "r"(dst), "l"(src));
}
#define CP_COMMIT() asm volatile("cp.async.commit_group;" ::: "memory")
#define CP_WAIT0()  asm volatile("cp.async.wait_group 0;" ::: "memory")
#define U(x) __float_as_uint(x)

// smem: As[2][128][40] | Bs[2][128][40] | Aptr[128]
#define LDW 40
#define OFF_B   40960
#define OFF_PTR 81920
#define SMEM_GEMM 82944

// issue one 128x32 A tile + 128x32 B tile stage via cp.async
__device__ __forceinline__ void issue_stage(uint32_t sb, const float* const* Aptr,
                                            const float* Bbase, size_t strideB,
                                            int k0, int s, int tid) {
#pragma unroll
    for (int i = 0; i < 4; i++) {
        int idx = tid + i * 256;
        int row = idx >> 3, col = (idx & 7) * 4;
        cp16(sb + (uint32_t)(((s * 128 + row) * LDW + col) * 4), Aptr[row] + k0 + col);
        cp16(sb + OFF_B + (uint32_t)(((s * 128 + row) * LDW + col) * 4),
             Bbase + (size_t)row * strideB + k0 + col);
    }
}

// compute 128x128x32; permuted-k fragments (float2 loads, raw fp32 -> tf32 trunc)
__device__ __forceinline__ void compute_tile(const float* As, const float* Bs,
                                             int warpM, int warpN, int g, int tg,
                                             float acc[4][4][4]) {
#pragma unroll
    for (int ks = 0; ks < 4; ks++) {
        int kk = ks * 8 + 2 * tg;
        uint32_t a[4][4];
#pragma unroll
        for (int mt = 0; mt < 4; mt++) {
            float2 lo = *(const float2*)&As[(warpM + mt * 16 + g) * LDW + kk];
            float2 hi = *(const float2*)&As[(warpM + mt * 16 + g + 8) * LDW + kk];
            a[mt][0] = U(lo.x); a[mt][1] = U(hi.x);
            a[mt][2] = U(lo.y); a[mt][3] = U(hi.y);
        }
#pragma unroll
        for (int nt = 0; nt < 4; nt++) {
            float2 bv = *(const float2*)&Bs[(warpN + nt * 8 + g) * LDW + kk];
            uint32_t b[2] = {U(bv.x), U(bv.y)};
#pragma unroll
            for (int mt = 0; mt < 4; mt++)
                mma8(acc[mt][nt], a[mt], b);
        }
    }
}

// ---------------- init ----------------
__global__ void init_kernel() {
    int t = threadIdx.x;
    if (t < NEXP) { g_cnt[t] = 0; g_usage[t] = 0.f; }
}

// ---------------- layernorm ----------------
__global__ void ln_kernel(const float* __restrict__ x, const float* __restrict__ g,
                          const float* __restrict__ b, float* __restrict__ y) {
    __shared__ float red[256];
    int row = blockIdx.x;
    const float* xr = x + (size_t)row * HD;
    float s = 0.f;
    for (int i = threadIdx.x; i < HD; i += 256) s += xr[i];
    red[threadIdx.x] = s; __syncthreads();
    for (int o = 128; o > 0; o >>= 1) {
        if (threadIdx.x < o) red[threadIdx.x] += red[threadIdx.x + o];
        __syncthreads();
    }
    float mu = red[0] * (1.f / HD);
    __syncthreads();
    float v = 0.f;
    for (int i = threadIdx.x; i < HD; i += 256) { float d = xr[i] - mu; v += d * d; }
    red[threadIdx.x] = v; __syncthreads();
    for (int o = 128; o > 0; o >>= 1) {
        if (threadIdx.x < o) red[threadIdx.x] += red[threadIdx.x + o];
        __syncthreads();
    }
    float rstd = rsqrtf(red[0] * (1.f / HD) + 1e-5f);
    float* yr = y + (size_t)row * HD;
    for (int i = threadIdx.x; i < HD; i += 256)
        yr[i] = (xr[i] - mu) * rstd * g[i] + b[i];
}

// ---------------- QKV projections ----------------
__global__ __launch_bounds__(256) void qkv_mma(const float* __restrict__ Wq,
                                               const float* __restrict__ Wk,
                                               const float* __restrict__ Wv) {
    extern __shared__ char sm[];
    float* As = (float*)sm;
    float* Bs = (float*)(sm + OFF_B);
    const float** Aptr = (const float**)(sm + OFF_PTR);
    int tid = threadIdx.x, wid = tid >> 5, lane = tid & 31;
    int g = lane >> 2, tg = lane & 3;
    int warpM = (wid >> 2) * 64, warpN = (wid & 3) * 32;
    const float* W = blockIdx.z == 0 ? Wq : (blockIdx.z == 1 ? Wk : Wv);
    float* C = blockIdx.z == 0 ? g_q : (blockIdx.z == 1 ? g_k : g_v);
    int rowBase = blockIdx.y * 128, colBase = blockIdx.x * 128;
    if (tid < 128) Aptr[tid] = g_h1 + (size_t)(rowBase + tid) * HD;
    __syncthreads();
    const float* Bbase = W + (size_t)colBase * HD;
    uint32_t sb = smem_u32(sm);
    float acc[4][4][4] = {};
    issue_stage(sb, Aptr, Bbase, HD, 0, 0, tid); CP_COMMIT();
    for (int kb = 0; kb < HD / 32; kb++) {
        CP_WAIT0(); __syncthreads();
        if (kb + 1 < HD / 32) { issue_stage(sb, Aptr, Bbase, HD, (kb + 1) * 32, (kb + 1) & 1, tid); CP_COMMIT(); }
        compute_tile((float*)sm + (kb & 1) * 128 * LDW, (float*)(sm + OFF_B) + (kb & 1) * 128 * LDW,
                     warpM, warpN, g, tg, acc);
        __syncthreads();
    }
#pragma unroll
    for (int mt = 0; mt < 4; mt++)
#pragma unroll
        for (int nt = 0; nt < 4; nt++) {
            int r0 = rowBase + warpM + mt * 16 + g;
            int c0 = colBase + warpN + nt * 8 + 2 * tg;
            *(float2*)(C + (size_t)r0 * HD + c0) = make_float2(acc[mt][nt][0], acc[mt][nt][1]);
            *(float2*)(C + (size_t)(r0 + 8) * HD + c0) = make_float2(acc[mt][nt][2], acc[mt][nt][3]);
        }
}

// ---------------- O projection + residual ----------------
__global__ __launch_bounds__(256) void oproj_mma(const float* __restrict__ Wo,
                                                 const float* __restrict__ xres) {
    extern __shared__ char sm[];
    const float** Aptr = (const float**)(sm + OFF_PTR);
    int tid = threadIdx.x, wid = tid >> 5, lane = tid & 31;
    int g = lane >> 2, tg = lane & 3;
    int warpM = (wid >> 2) * 64, warpN = (wid & 3) * 32;
    int rowBase = blockIdx.y * 128, colBase = blockIdx.x * 128;
    if (tid < 128) Aptr[tid] = g_attn + (size_t)(rowBase + tid) * HD;
    __syncthreads();
    const float* Bbase = Wo + (size_t)colBase * HD;
    uint32_t sb = smem_u32(sm);
    float acc[4][4][4] = {};
    issue_stage(sb, Aptr, Bbase, HD, 0, 0, tid); CP_COMMIT();
    for (int kb = 0; kb < HD / 32; kb++) {
        CP_WAIT0(); __syncthreads();
        if (kb + 1 < HD / 32) { issue_stage(sb, Aptr, Bbase, HD, (kb + 1) * 32, (kb + 1) & 1, tid); CP_COMMIT(); }
        compute_tile((float*)sm + (kb & 1) * 128 * LDW, (float*)(sm + OFF_B) + (kb & 1) * 128 * LDW,
                     warpM, warpN, g, tg, acc);
        __syncthreads();
    }
#pragma unroll
    for (int mt = 0; mt < 4; mt++)
#pragma unroll
        for (int nt = 0; nt < 4; nt++) {
            int r0 = rowBase + warpM + mt * 16 + g;
            int c0 = colBase + warpN + nt * 8 + 2 * tg;
            float2 a = *(const float2*)(xres + (size_t)r0 * HD + c0);
            float2 b = *(const float2*)(xres + (size_t)(r0 + 8) * HD + c0);
            *(float2*)(g_x1 + (size_t)r0 * HD + c0) = make_float2(acc[mt][nt][0] + a.x, acc[mt][nt][1] + a.y);
            *(float2*)(g_x1 + (size_t)(r0 + 8) * HD + c0) = make_float2(acc[mt][nt][2] + b.x, acc[mt][nt][3] + b.y);
        }
}

// ---------------- flash attention (causal, tf32 mma) ----------------
// block: 128 q-rows, 8 warps x 16 rows; key tiles of 64.
#define AQR 128
#define ALD 72
__global__ __launch_bounds__(256) void attn_mma() {
    extern __shared__ char sm[];
    float* smf = (float*)sm;
    float* Qs = smf;              // [128][72]
    float* Ks = smf + 128 * ALD;  // [64][72]   (key-major, [key][dh])
    float* Vt = smf + 192 * ALD;  // [64][72]   (transposed, [dh][key])
    int qb = gridDim.x - 1 - blockIdx.x;  // heavy blocks first
    int bh = blockIdx.y;
    int b = bh >> 4, h = bh & 15;
    int tid = threadIdx.x, wid = tid >> 5, lane = tid & 31;
    int g = lane >> 2, tg = lane & 3;
    int qr0 = wid * 16;
    const float* qbase = g_q + (size_t)(b * SEQ + qb * AQR) * HD + h * DH;
#pragma unroll
    for (int i = 0; i < 8; i++) {
        int idx = tid + i * 256;
        int row = idx >> 4, c = (idx & 15) * 4;
        *(float4*)&Qs[row * ALD + c] = *(const float4*)(qbase + (size_t)row * HD + c);
    }
    float m0 = -1e30f, m1 = -1e30f, l0 = 0.f, l1 = 0.f;
    float o[8][4] = {};
    int nkt = qb * 2 + 2;
    int rmaxWarp = qb * AQR + qr0 + 15;
    for (int kt = 0; kt < nkt; kt++) {
        __syncthreads();
        const float* kbase = g_k + (size_t)(b * SEQ + kt * 64) * HD + h * DH;
        const float* vbase = g_v + (size_t)(b * SEQ + kt * 64) * HD + h * DH;
#pragma unroll
        for (int i = 0; i < 4; i++) {
            int idx = tid + i * 256;
            int row = idx >> 4, c = (idx & 15) * 4;
            *(float4*)&Ks[row * ALD + c] = *(const float4*)(kbase + (size_t)row * HD + c);
        }
#pragma unroll
        for (int i = 0; i < 4; i++) {
            int idx = tid + i * 256;
            int key = idx & 63, c0 = (idx >> 6) * 4;
            float4 v = *(const float4*)(vbase + (size_t)key * HD + c0);
            Vt[(c0 + 0) * ALD + key] = v.x;
            Vt[(c0 + 1) * ALD + key] = v.y;
            Vt[(c0 + 2) * ALD + key] = v.z;
            Vt[(c0 + 3) * ALD + key] = v.w;
        }
        __syncthreads();
        if (kt * 64 > rmaxWarp) continue;   // fully masked for this warp
        // S = Q K^T  (16 x 64)
        float s[8][4] = {};
#pragma unroll
        for (int ks = 0; ks < 8; ks++) {
            int kk = ks * 8 + 2 * tg;
            float2 alo = *(const float2*)&Qs[(qr0 + g) * ALD + kk];
            float2 ahi = *(const float2*)&Qs[(qr0 + g + 8) * ALD + kk];
            uint32_t ar[4] = {U(alo.x), U(ahi.x), U(alo.y), U(ahi.y)};
#pragma unroll
            for (int nt = 0; nt < 8; nt++) {
                float2 bv = *(const float2*)&Ks[(nt * 8 + g) * ALD + kk];
                uint32_t br[2] = {U(bv.x), U(bv.y)};
                mma8(s[nt], ar, br);
            }
        }
        // scale + causal mask
        int r0 = qb * AQR + qr0 + g, r1 = r0 + 8;
#pragma unroll
        for (int nt = 0; nt < 8; nt++) {
            int c = kt * 64 + nt * 8 + 2 * tg;
            s[nt][0] = (c     > r0) ? -1e30f : s[nt][0] * 0.125f;
            s[nt][1] = (c + 1 > r0) ? -1e30f : s[nt][1] * 0.125f;
            s[nt][2] = (c     > r1) ? -1e30f : s[nt][2] * 0.125f;
            s[nt][3] = (c + 1 > r1) ? -1e30f : s[nt][3] * 0.125f;
        }
        // online softmax (rows r0: regs 0,1; r1: regs 2,3)
        float mx0 = -1e30f, mx1 = -1e30f;
#pragma unroll
        for (int nt = 0; nt < 8; nt++) {
            mx0 = fmaxf(mx0, fmaxf(s[nt][0], s[nt][1]));
            mx1 = fmaxf(mx1, fmaxf(s[nt][2], s[nt][3]));
        }
        mx0 = fmaxf(mx0, __shfl_xor_sync(0xffffffffu, mx0, 1));
        mx0 = fmaxf(mx0, __shfl_xor_sync(0xffffffffu, mx0, 2));
        mx1 = fmaxf(mx1, __shfl_xor_sync(0xffffffffu, mx1, 1));
        mx1 = fmaxf(mx1, __shfl_xor_sync(0xffffffffu, mx1, 2));
        float mn0 = fmaxf(m0, mx0), mn1 = fmaxf(m1, mx1);
        float rs0 = 0.f, rs1 = 0.f;
#pragma unroll
        for (int nt = 0; nt < 8; nt++) {
            s[nt][0] = __expf(s[nt][0] - mn0); rs0 += s[nt][0];
            s[nt][1] = __expf(s[nt][1] - mn0); rs0 += s[nt][1];
            s[nt][2] = __expf(s[nt][2] - mn1); rs1 += s[nt][2];
            s[nt][3] = __expf(s[nt][3] - mn1); rs1 += s[nt][3];
        }
        rs0 += __shfl_xor_sync(0xffffffffu, rs0, 1);
        rs0 += __shfl_xor_sync(0xffffffffu, rs0, 2);
        rs1 += __shfl_xor_sync(0xffffffffu, rs1, 1);
        rs1 += __shfl_xor_sync(0xffffffffu, rs1, 2);
        float al0 = __expf(m0 - mn0), al1 = __expf(m1 - mn1);
        m0 = mn0; m1 = mn1;
        l0 = l0 * al0 + rs0; l1 = l1 * al1 + rs1;
#pragma unroll
        for (int nt = 0; nt < 8; nt++) {
            o[nt][0] *= al0; o[nt][1] *= al0;
            o[nt][2] *= al1; o[nt][3] *= al1;
        }
        // O += P V   (P stays in registers; C-frag == permuted-k A-frag)
#pragma unroll
        for (int ks = 0; ks < 8; ks++) {
            uint32_t ar[4] = {U(s[ks][0]), U(s[ks][2]), U(s[ks][1]), U(s[ks][3])};
            int kk = ks * 8 + 2 * tg;
#pragma unroll
            for (int nt = 0; nt < 8; nt++) {
                float2 bv = *(const float2*)&Vt[(nt * 8 + g) * ALD + kk];
                uint32_t br[2] = {U(bv.x), U(bv.y)};
                mma8(o[nt], ar, br);
            }
        }
    }
    float i0 = 1.f / l0, i1 = 1.f / l1;
    float* obase = g_attn + (size_t)(b * SEQ + qb * AQR + qr0) * HD + h * DH;
#pragma unroll
    for (int nt = 0; nt < 8; nt++) {
        int c = nt * 8 + 2 * tg;
        *(float2*)(obase + (size_t)g * HD + c)       = make_float2(o[nt][0] * i0, o[nt][1] * i0);
        *(float2*)(obase + (size_t)(g + 8) * HD + c) = make_float2(o[nt][2] * i1, o[nt][3] * i1);
    }
}

// ---------------- router ----------------
__global__ void router_kernel(const float* __restrict__ Wr) {
    int gwarp = (blockIdx.x * blockDim.x + threadIdx.x) >> 5;
    int lane = threadIdx.x & 31;
    if (gwarp >= TOK) return;
    const float* xr = g_h2 + (size_t)gwarp * HD;
    float acc[NEXP] = {};
    for (int i = lane; i < HD; i += 32) {
        float xv = xr[i];
#pragma unroll
        for (int e = 0; e < NEXP; e++) acc[e] += xv * Wr[e * HD + i];
    }
#pragma unroll
    for (int e = 0; e < NEXP; e++)
#pragma unroll
        for (int o = 16; o > 0; o >>= 1)
            acc[e] += __shfl_xor_sync(0xffffffffu, acc[e], o);
    if (lane == 0) {
        float mx = acc[0];
#pragma unroll
        for (int e = 1; e < NEXP; e++) mx = fmaxf(mx, acc[e]);
        float p[NEXP], se = 0.f;
#pragma unroll
        for (int e = 0; e < NEXP; e++) { p[e] = __expf(acc[e] - mx); se += p[e]; }
        float inv = 1.f / (se * (float)TOK);
#pragma unroll
        for (int e = 0; e < NEXP; e++) atomicAdd(&g_usage[e], p[e] * inv);
        int i0 = 0;
#pragma unroll
        for (int e = 1; e < NEXP; e++) if (acc[e] > acc[i0]) i0 = e;
        int i1 = (i0 == 0) ? 1 : 0;
#pragma unroll
        for (int e = 0; e < NEXP; e++) if (e != i0 && acc[e] > acc[i1]) i1 = e;
        float l0 = acc[i0], l1 = acc[i1];
        float m2 = fmaxf(l0, l1);
        float e0 = __expf(l0 - m2), e1 = __expf(l1 - m2);
        float s2 = e0 + e1;
        g_we[gwarp * NEXP + i0] = e0 / s2;
        g_we[gwarp * NEXP + i1] = e1 / s2;
        int p0 = atomicAdd(&g_cnt[i0], 1); g_idx[i0 * TOK + p0] = gwarp;
        int p1 = atomicAdd(&g_cnt[i1], 1); g_idx[i1 * TOK + p1] = gwarp;
    }
}

// ---------------- MoE up ----------------
__global__ __launch_bounds__(256) void moe_up_mma(const float* __restrict__ W1,
                                                  const float* __restrict__ W3) {
    extern __shared__ char sm[];
    int e = blockIdx.z;
    int cnt = g_cnt[e];
    int rowBase = blockIdx.y * 128;
    if (rowBase >= cnt) return;
    int half = blockIdx.x >> 5;
    int colBase = (blockIdx.x & 31) * 128;
    const float* W = half ? W3 : W1;
    float* dstb = half ? g_hgB : g_hgA;
    const float** Aptr = (const float**)(sm + OFF_PTR);
    int tid = threadIdx.x, wid = tid >> 5, lane = tid & 31;
    int g = lane >> 2, tg = lane & 3;
    int warpM = (wid >> 2) * 64, warpN = (wid & 3) * 32;
    if (tid < 128) {
        int p = rowBase + tid;
        Aptr[tid] = g_h2 + (size_t)g_idx[e * TOK + (p < cnt ? p : cnt - 1)] * HD;
    }
    __syncthreads();
    const float* Bbase = W + (size_t)e * FF * HD + (size_t)colBase * HD;
    uint32_t sb = smem_u32(sm);
    float acc[4][4][4] = {};
    issue_stage(sb, Aptr, Bbase, HD, 0, 0, tid); CP_COMMIT();
    for (int kb = 0; kb < HD / 32; kb++) {
        CP_WAIT0(); __syncthreads();
        if (kb + 1 < HD / 32) { issue_stage(sb, Aptr, Bbase, HD, (kb + 1) * 32, (kb + 1) & 1, tid); CP_COMMIT(); }
        compute_tile((float*)sm + (kb & 1) * 128 * LDW, (float*)(sm + OFF_B) + (kb & 1) * 128 * LDW,
                     warpM, warpN, g, tg, acc);
        __syncthreads();
    }
#pragma unroll
    for (int mt = 0; mt < 4; mt++)
#pragma unroll
        for (int nt = 0; nt < 4; nt++) {
            int p0 = rowBase + warpM + mt * 16 + g;
            int c0 = colBase + warpN + nt * 8 + 2 * tg;
            if (p0 < cnt)
                *(float2*)(dstb + ((size_t)e * TOK + p0) * FF + c0) =
                    make_float2(acc[mt][nt][0], acc[mt][nt][1]);
            if (p0 + 8 < cnt)
                *(float2*)(dstb + ((size_t)e * TOK + p0 + 8) * FF + c0) =
                    make_float2(acc[mt][nt][2], acc[mt][nt][3]);
        }
}

// ---------------- silu * mul ----------------
__global__ void silu_mul_kernel() {
    int e = blockIdx.y;
    int cnt = g_cnt[e];
    int pos = blockIdx.x;
    if (pos >= cnt) return;
    size_t off = ((size_t)e * TOK + pos) * FF;
    for (int i = threadIdx.x; i < FF / 4; i += 256) {
        float4 a = *(const float4*)(g_hgA + off + (size_t)i * 4);
        float4 b = *(const float4*)(g_hgB + off + (size_t)i * 4);
        a.x = a.x / (1.f + __expf(-a.x)) * b.x;
        a.y = a.y / (1.f + __expf(-a.y)) * b.y;
        a.z = a.z / (1.f + __expf(-a.z)) * b.z;
        a.w = a.w / (1.f + __expf(-a.w)) * b.w;
        *(float4*)(g_hgA + off + (size_t)i * 4) = a;
    }
}

// ---------------- MoE down (scatter-atomic) ----------------
__global__ __launch_bounds__(256) void moe_down_mma(const float* __restrict__ W2,
                                                    float* __restrict__ out) {
    extern __shared__ char sm[];
    int e = blockIdx.z;
    int cnt = g_cnt[e];
    int rowBase = blockIdx.y * 128;
    if (rowBase >= cnt) return;
    int colBase = blockIdx.x * 128;
    const float** Aptr = (const float**)(sm + OFF_PTR);
    int tid = threadIdx.x, wid = tid >> 5, lane = tid & 31;
    int g = lane >> 2, tg = lane & 3;
    int warpM = (wid >> 2) * 64, warpN = (wid & 3) * 32;
    if (tid < 128)
        Aptr[tid] = g_hgA + ((size_t)e * TOK + rowBase + tid) * FF;
    __syncthreads();
    const float* Bbase = W2 + (size_t)e * HD * FF + (size_t)colBase * FF;
    uint32_t sb = smem_u32(sm);
    float acc[4][4][4] = {};
    issue_stage(sb, Aptr, Bbase, FF, 0, 0, tid); CP_COMMIT();
    for (int kb = 0; kb < FF / 32; kb++) {
        CP_WAIT0(); __syncthreads();
        if (kb + 1 < FF / 32) { issue_stage(sb, Aptr, Bbase, FF, (kb + 1) * 32, (kb + 1) & 1, tid); CP_COMMIT(); }
        compute_tile((float*)sm + (kb & 1) * 128 * LDW, (float*)(sm + OFF_B) + (kb & 1) * 128 * LDW,
                     warpM, warpN, g, tg, acc);
        __syncthreads();
    }
#pragma unroll
    for (int mt = 0; mt < 4; mt++) {
        int p0 = rowBase + warpM + mt * 16 + g;
        int p1 = p0 + 8;
        int t0 = 0, t1 = 0; float w0 = 0.f, w1 = 0.f;
        if (p0 < cnt) { t0 = g_idx[e * TOK + p0]; w0 = g_we[t0 * NEXP + e]; }
        if (p1 < cnt) { t1 = g_idx[e * TOK + p1]; w1 = g_we[t1 * NEXP + e]; }
#pragma unroll
        for (int nt = 0; nt < 4; nt++) {
            int c0 = colBase + warpN + nt * 8 + 2 * tg;
            if (p0 < cnt) {
                atomicAdd(out + (size_t)t0 * HD + c0,     w0 * acc[mt][nt][0]);
                atomicAdd(out + (size_t)t0 * HD + c0 + 1, w0 * acc[mt][nt][1]);
            }
            if (p1 < cnt) {
                atomicAdd(out + (size_t)t1 * HD + c0,     w1 * acc[mt][nt][2]);
                atomicAdd(out + (size_t)t1 * HD + c0 + 1, w1 * acc[mt][nt][3]);
            }
        }
    }
}

// ---------------- residual copy / lb ----------------
__global__ void copy_kernel(float* __restrict__ out) {
    int i = blockIdx.x * 256 + threadIdx.x;
    *(float4*)(out + (size_t)i * 4) = *(const float4*)(g_x1 + (size_t)i * 4);
}
__global__ void lb_kernel(float* __restrict__ out) {
    if (threadIdx.x == 0) {
        float s = 0.f;
#pragma unroll
        for (int e = 0; e < NEXP; e++) s += g_usage[e] * g_usage[e];
        out[(size_t)TOK * HD] = (float)NEXP * s;
    }
}

// ---------------- launch ----------------
extern "C" void kernel_launch(void* const* d_in, const int* in_sizes, int n_in,
                              void* d_out, int out_size) {
    const float* x    = (const float*)d_in[0];
    const float* Wq   = (const float*)d_in[1];
    const float* Wk   = (const float*)d_in[2];
    const float* Wv   = (const float*)d_in[3];
    const float* Wo   = (const float*)d_in[4];
    const float* ln1g = (const float*)d_in[5];
    const float* ln1b = (const float*)d_in[6];
    const float* ln2g = (const float*)d_in[7];
    const float* ln2b = (const float*)d_in[8];
    const float* Wr   = (const float*)d_in[9];
    const float* W1   = (const float*)d_in[10];
    const float* W2   = (const float*)d_in[11];
    const float* W3   = (const float*)d_in[12];
    float* out = (float*)d_out;

    float *ph1, *px1, *ph2;
    cudaGetSymbolAddress((void**)&ph1, g_h1);
    cudaGetSymbolAddress((void**)&px1, g_x1);
    cudaGetSymbolAddress((void**)&ph2, g_h2);

    const int SMEM_ATTN = 256 * ALD * (int)sizeof(float);  // 73728
    cudaFuncSetAttribute(qkv_mma,      cudaFuncAttributeMaxDynamicSharedMemorySize, SMEM_GEMM);
    cudaFuncSetAttribute(oproj_mma,    cudaFuncAttributeMaxDynamicSharedMemorySize, SMEM_GEMM);
    cudaFuncSetAttribute(moe_up_mma,   cudaFuncAttributeMaxDynamicSharedMemorySize, SMEM_GEMM);
    cudaFuncSetAttribute(moe_down_mma, cudaFuncAttributeMaxDynamicSharedMemorySize, SMEM_GEMM);
    cudaFuncSetAttribute(attn_mma,     cudaFuncAttributeMaxDynamicSharedMemorySize, SMEM_ATTN);

    init_kernel<<<1, 32>>>();
    ln_kernel<<<TOK, 256>>>(x, ln1g, ln1b, ph1);
    qkv_mma<<<dim3(HD / 128, TOK / 128, 3), 256, SMEM_GEMM>>>(Wq, Wk, Wv);
    attn_mma<<<dim3(SEQ / AQR, 2 * NHEAD), 256, SMEM_ATTN>>>();
    oproj_mma<<<dim3(HD / 128, TOK / 128), 256, SMEM_GEMM>>>(Wo, x);
    ln_kernel<<<TOK, 256>>>(px1, ln2g, ln2b, ph2);
    router_kernel<<<TOK / 8, 256>>>(Wr);
    copy_kernel<<<TOK * HD / 1024, 256>>>(out);
    moe_up_mma<<<dim3(2 * FF / 128, TOK / 128, NEXP), 256, SMEM_GEMM>>>(W1, W3);
    silu_mul_kernel<<<dim3(TOK, NEXP), 256>>>();
    moe_down_mma<<<dim3(HD / 128, TOK / 128, NEXP), 256, SMEM_GEMM>>>(W2, out);
    if ((long long)out_size >= (long long)TOK * HD + 1)
        lb_kernel<<<1, 32>>>(out);
}